// round 16
// baseline (speedup 1.0000x reference)
#include <cuda_runtime.h>

// Antialiased bilinear (triangle) 4x downsample — vertical-first separable,
// persistent CTAs + L2 prefetch of the next tile (register-free pipelining).
// x: (2048,6,128,96) f32 -> out: (2048,6,32,24) f32 (= (B,6,768))
//
// Tile = half an image (16 output rows); 24576 tiles walked grid-stride by
// 608 persistent CTAs (4/SM * 152 SMs). Per tile, each warp owns 2 output
// rows: hoists its 12 input rows (LDG.128, lane<24), then immediately posts
// prefetch.global.L2 for the SAME warp's 12 rows of its next tile (36 x
// 128B lines via 2 predicated prefetches/thread, no registers), then does
// vertical 8-tap (12 rows -> 2 packed rows, no shuffles) and horizontal
// 8-tap via partial-sum exchange (2 shuffles/row). OOB taps dropped +
// renormalized == jax antialias; clamped rows corrected exactly by linearity.

#define IN_H  128
#define IN_W  96
#define OUT_H 32
#define OUT_W 24
#define NT    (12288 * 2)     // image-half tiles
#define GRID  608             // 4 CTAs/SM * 152 SMs

__global__ __launch_bounds__(256, 4)
void resize_aa_kernel(const float* __restrict__ x, float* __restrict__ out)
{
    const int lane = threadIdx.x & 31;
    const int warp = threadIdx.x >> 5;              // 0..7
    const bool  act   = lane < OUT_W;

    const float m0    = (lane == 0) ? 0.f : 1.f;            // mask shfl_up garbage
    const float inv_s = (lane == 0 || lane == OUT_W - 1) ? (1.f / 3.5f) : 0.25f;

    for (int t = blockIdx.x; t < NT; t += GRID) {
        const size_t img  = (size_t)(t >> 1);
        const int   half  = t & 1;
        const int   or0   = half * 16 + 2 * warp;   // first of 2 output rows
        const int   rbase = 4 * or0 - 2;            // first input row needed

        const float* __restrict__ ip = x + img * (size_t)(IN_H * IN_W);

        // ---- PHASE 1: hoist all 12 row loads (independent LDG.128s) ----
        float4 v[12];
#pragma unroll
        for (int i = 0; i < 12; ++i) {
            int r = rbase + i;
            r = r < 0 ? 0 : (r > IN_H - 1 ? IN_H - 1 : r);   // clamp (fixed below)
            v[i] = act ? ((const float4*)(ip + (size_t)r * IN_W))[lane]
                       : make_float4(0.f, 0.f, 0.f, 0.f);
        }

        // ---- PHASE 1b: L2-prefetch this warp's rows of its NEXT tile ----
        // 12 rows x 384B = 36 lines of 128B; 2 predicated prefetches/thread.
        {
            const int tn = t + GRID;
            if (tn < NT) {
                const size_t imgn = (size_t)(tn >> 1);
                const int    or0n = (tn & 1) * 16 + 2 * warp;
                const int    rbn  = 4 * or0n - 2;
                const char* __restrict__ bp =
                    (const char*)(x + imgn * (size_t)(IN_H * IN_W));
#pragma unroll
                for (int q = 0; q < 2; ++q) {
                    const int idx = lane + q * 32;
                    if (idx < 36) {
                        int rr = rbn + idx / 3;
                        rr = rr < 0 ? 0 : (rr > IN_H - 1 ? IN_H - 1 : rr);
                        const char* pa = bp + (size_t)rr * (IN_W * 4) + (idx % 3) * 128;
                        asm volatile("prefetch.global.L2 [%0];" :: "l"(pa));
                    }
                }
            }
        }

        // ---- PHASE 2: vertical 8-tap on raw columns (12 rows -> 2 rows) ----
        // raw taps tri(k) = {.125,.375,.625,.875,.875,.625,.375,.125}
        float4 a0 = make_float4(0.f, 0.f, 0.f, 0.f);
        float4 a1 = make_float4(0.f, 0.f, 0.f, 0.f);
#pragma unroll
        for (int i = 0; i < 12; ++i) {
            if (i < 8) {
                const float wv = 1.f - fabsf((float)i - 3.5f) * 0.25f;        // imm
                a0.x = fmaf(v[i].x, wv, a0.x);
                a0.y = fmaf(v[i].y, wv, a0.y);
                a0.z = fmaf(v[i].z, wv, a0.z);
                a0.w = fmaf(v[i].w, wv, a0.w);
            }
            if (i >= 4) {
                const float wv = 1.f - fabsf((float)(i - 4) - 3.5f) * 0.25f;  // imm
                a1.x = fmaf(v[i].x, wv, a1.x);
                a1.y = fmaf(v[i].y, wv, a1.y);
                a1.z = fmaf(v[i].z, wv, a1.z);
                a1.w = fmaf(v[i].w, wv, a1.w);
            }
        }

        // ---- vertical edge correction (exact, uniform per warp) ----
        float n0 = 0.25f, n1 = 0.25f;
        if (or0 == 0) {                              // rows -2,-1 were dupes of row 0
            a0.x -= fmaf(v[0].x, 0.125f, v[1].x * 0.375f);
            a0.y -= fmaf(v[0].y, 0.125f, v[1].y * 0.375f);
            a0.z -= fmaf(v[0].z, 0.125f, v[1].z * 0.375f);
            a0.w -= fmaf(v[0].w, 0.125f, v[1].w * 0.375f);
            n0 = 1.f / 3.5f;
        }
        if (or0 + 1 == OUT_H - 1) {                  // rows 128,129 dupes of 127
            a1.x -= fmaf(v[10].x, 0.375f, v[11].x * 0.125f);
            a1.y -= fmaf(v[10].y, 0.375f, v[11].y * 0.125f);
            a1.z -= fmaf(v[10].z, 0.375f, v[11].z * 0.125f);
            a1.w -= fmaf(v[10].w, 0.375f, v[11].w * 0.125f);
            n1 = 1.f / 3.5f;
        }

        // ---- PHASE 3: horizontal 8-tap on the 2 collapsed rows ----
        float* __restrict__ op = out + img * (size_t)(OUT_H * OUT_W);
#pragma unroll
        for (int o = 0; o < 2; ++o) {
            const float4 a = o ? a1 : a0;
            const float  nv = o ? n1 : n0;

            float pR = a.z * 0.125f; pR = fmaf(a.w, 0.375f, pR);   // -> lane+1
            float pL = a.x * 0.375f; pL = fmaf(a.y, 0.125f, pL);   // -> lane-1
            const float rcvU = __shfl_up_sync(0xffffffffu, pR, 1);
            const float rcvD = __shfl_down_sync(0xffffffffu, pL, 1); // 0 at lane 23

            float h;
            h = a.x * 0.625f;
            h = fmaf(a.y, 0.875f, h);
            h = fmaf(a.z, 0.875f, h);
            h = fmaf(a.w, 0.625f, h);
            h += rcvD;
            h = fmaf(rcvU, m0, h);          // mask lane-0 up-shuffle garbage

            if (act) op[(or0 + o) * OUT_W + lane] = h * (inv_s * nv);
        }
    }
}

extern "C" void kernel_launch(void* const* d_in, const int* in_sizes, int n_in,
                              void* d_out, int out_size)
{
    const float* x = (const float*)d_in[0];   // (2048,6,128,96) f32; d_in[1] unused
    float* out = (float*)d_out;               // (2048,6,768) f32
    resize_aa_kernel<<<GRID, 256>>>(x, out);
}